// round 3
// baseline (speedup 1.0000x reference)
#include <cuda_runtime.h>
#include <cuda_bf16.h>
#include <cstdint>
#include <cstddef>

#define NB   4
#define NC   64
#define NL   4096
#define NH   128
#define NKE  192          // [hi|x|x] split-bf16 extended K dimension

#define SCALE_LOG2E 14.4269504088896340737f   // 10 * log2(e)
#define THRESH 1e-3f

// ---------------- device scratch (no allocations allowed) ----------------
__device__ __align__(256) __nv_bfloat16 g_Q[NB*NL*NKE];   // [b][l][192] = [qhi|qlo|qhi]
__device__ __align__(256) __nv_bfloat16 g_K[NB*NL*NKE];   // [b][l][192] = [khi|khi|klo]

// ---------------- projection + leakyrelu + projection + l2norm + bf16 split ----------------
#define PJ_POS 32
#define HS_STR 132
#define SA_W1 0
#define SA_W2 (NC*NH)                    // 8192 floats
#define SA_XS (SA_W2 + NH*NC)            // 16384
#define SA_HS (SA_XS + NC*PJ_POS)        // 18432
#define SA_FLOATS (SA_HS + PJ_POS*HS_STR)
#define SA_BYTES (SA_FLOATS*4)

__global__ void __launch_bounds__(256) proj_kernel(const float* __restrict__ xq,
                                                   const float* __restrict__ xk,
                                                   const float* __restrict__ W1,
                                                   const float* __restrict__ W2){
  extern __shared__ float sm_f[];
  float* sm = sm_f;
  const int tid = threadIdx.x;
  const int bpt = NL / PJ_POS;                 // 128 blocks per (tensor,batch)
  const int tb  = blockIdx.x / bpt;            // 0..7  (0..3 = query, 4..7 = key)
  const int l0  = (blockIdx.x % bpt) * PJ_POS;
  const bool isQ = (tb < NB);
  const int b   = tb & 3;
  const float* __restrict__ src = isQ ? xq : xk;
  __nv_bfloat16* __restrict__ dst = isQ ? g_Q : g_K;

  // transposed weight loads (W is tiny & L2-resident; smem writes conflict-free)
  for (int i = tid; i < NH*NC; i += 256){
    int j = i & 127, c = i >> 7;
    sm[SA_W1 + c*NH + j] = W1[j*NC + c];       // W1t[c][j], consecutive j per tid
  }
  for (int i = tid; i < NH*NC; i += 256){
    int o = i & 63, j = i >> 6;
    sm[SA_W2 + j*NC + o] = W2[o*NH + j];       // W2t[j][o], consecutive o per tid
  }
  for (int i = tid; i < NC*PJ_POS; i += 256){
    int c = i >> 5, p = i & 31;
    sm[SA_XS + i] = src[((size_t)b*NC + c)*NL + l0 + p];   // xs[c][p]
  }
  __syncthreads();

  const int lanegrp = tid & 31;   // jg in phase1, og in phase2
  const int pg      = tid >> 5;   // 0..7 (4 positions each)

  // ---- phase 1: h = leakyrelu(W1 @ x) ----
  {
    float acc[4][4];
    #pragma unroll
    for (int ji=0;ji<4;ji++){
      #pragma unroll
      for (int pi=0;pi<4;pi++) acc[ji][pi]=0.f;
    }
    #pragma unroll 4
    for (int c=0;c<NC;c++){
      const float4 w = *(const float4*)&sm[SA_W1 + c*NH + lanegrp*4];
      const float* xr = &sm[SA_XS + c*PJ_POS + pg*4];
      float x0 = xr[0], x1 = xr[1], x2 = xr[2], x3 = xr[3];
      acc[0][0] += w.x*x0; acc[1][0] += w.y*x0; acc[2][0] += w.z*x0; acc[3][0] += w.w*x0;
      acc[0][1] += w.x*x1; acc[1][1] += w.y*x1; acc[2][1] += w.z*x1; acc[3][1] += w.w*x1;
      acc[0][2] += w.x*x2; acc[1][2] += w.y*x2; acc[2][2] += w.z*x2; acc[3][2] += w.w*x2;
      acc[0][3] += w.x*x3; acc[1][3] += w.y*x3; acc[2][3] += w.z*x3; acc[3][3] += w.w*x3;
    }
    #pragma unroll
    for (int pi=0;pi<4;pi++){
      float4 h;
      h.x = acc[0][pi] >= 0.f ? acc[0][pi] : 0.01f*acc[0][pi];
      h.y = acc[1][pi] >= 0.f ? acc[1][pi] : 0.01f*acc[1][pi];
      h.z = acc[2][pi] >= 0.f ? acc[2][pi] : 0.01f*acc[2][pi];
      h.w = acc[3][pi] >= 0.f ? acc[3][pi] : 0.01f*acc[3][pi];
      *(float4*)&sm[SA_HS + (pg*4+pi)*HS_STR + lanegrp*4] = h;
    }
  }
  __syncthreads();

  // ---- phase 2: y = W2 @ h ; normalize ; split to bf16 ----
  {
    float acc[2][4];
    #pragma unroll
    for (int oi=0;oi<2;oi++){
      #pragma unroll
      for (int pi=0;pi<4;pi++) acc[oi][pi]=0.f;
    }
    #pragma unroll 4
    for (int j=0;j<NH;j++){
      float w0 = sm[SA_W2 + j*NC + lanegrp];
      float w1 = sm[SA_W2 + j*NC + lanegrp + 32];
      const float* hr = &sm[SA_HS + pg*4*HS_STR + j];
      #pragma unroll
      for (int pi=0;pi<4;pi++){
        float hv = hr[pi*HS_STR];
        acc[0][pi] += w0*hv;
        acc[1][pi] += w1*hv;
      }
    }
    #pragma unroll
    for (int pi=0;pi<4;pi++){
      float ssq = acc[0][pi]*acc[0][pi] + acc[1][pi]*acc[1][pi];
      #pragma unroll
      for (int off=16; off; off>>=1) ssq += __shfl_xor_sync(0xffffffffu, ssq, off);
      float inv = 1.0f / fmaxf(sqrtf(ssq), 1e-12f);
      int p = pg*4 + pi;
      size_t rowbase = ((size_t)b*NL + l0 + p) * NKE;
      #pragma unroll
      for (int oi=0;oi<2;oi++){
        int o = lanegrp + oi*32;
        float v = acc[oi][pi] * inv;
        __nv_bfloat16 hi = __float2bfloat16(v);
        __nv_bfloat16 lo = __float2bfloat16(v - __bfloat162float(hi));
        if (isQ){
          dst[rowbase + o]       = hi;   // seg0: qhi
          dst[rowbase + 64 + o]  = lo;   // seg1: qlo
          dst[rowbase + 128 + o] = hi;   // seg2: qhi
        } else {
          dst[rowbase + o]       = hi;   // seg0: khi
          dst[rowbase + 64 + o]  = hi;   // seg1: khi
          dst[rowbase + 128 + o] = lo;   // seg2: klo
        }
      }
    }
  }
}

// ---------------- attention: scores GEMM + softmax + threshold ----------------
#define CHUNK 128
#define NCH   (NL/CHUNK)     // 32
#define SROW_B 400           // padded smem row stride (192*2=384 data + 16 pad)
#define SQ_OFF  0
#define SK0_OFF 51200
#define SK1_OFF 102400
#define SRS_OFF 153600       // float rsum[2][128]
#define SINV_OFF 154624      // float inv[128]
#define SB_TOTAL 155136

__device__ __forceinline__ float fexp2(float x){
  float y;
  asm("ex2.approx.ftz.f32 %0, %1;" : "=f"(y) : "f"(x));
  return y;
}

__device__ __forceinline__ void cpa16(void* sptr, const void* gptr){
  uint32_t s = (uint32_t)__cvta_generic_to_shared(sptr);
  asm volatile("cp.async.cg.shared.global [%0], [%1], 16;" :: "r"(s), "l"(gptr));
}
__device__ __forceinline__ void cpcommit(){ asm volatile("cp.async.commit_group;"); }
__device__ __forceinline__ void cpwait1(){ asm volatile("cp.async.wait_group 1;"); }

// stage 128 rows of 384B (global, dense) into smem (stride 400B)
__device__ __forceinline__ void stage_tile(char* sdst, const __nv_bfloat16* gsrc, int tid){
  const char* gb = (const char*)gsrc;
  #pragma unroll
  for (int i = 0; i < 12; i++){
    int idx = tid + i*256;
    int r = idx / 24, o = idx % 24;
    cpa16(sdst + r*SROW_B + o*16, gb + (size_t)r*384 + o*16);
  }
}

__device__ __forceinline__ void ldsm4(uint32_t (&r)[4], uint32_t saddr){
  asm volatile("ldmatrix.sync.aligned.m8n8.x4.shared.b16 {%0,%1,%2,%3}, [%4];"
    : "=r"(r[0]), "=r"(r[1]), "=r"(r[2]), "=r"(r[3]) : "r"(saddr));
}

__device__ __forceinline__ void mma16816(float (&c)[4], const uint32_t (&a)[4],
                                         uint32_t b0, uint32_t b1){
  asm volatile(
    "mma.sync.aligned.m16n8k16.row.col.f32.bf16.bf16.f32 "
    "{%0,%1,%2,%3}, {%4,%5,%6,%7}, {%8,%9}, {%0,%1,%2,%3};"
    : "+f"(c[0]), "+f"(c[1]), "+f"(c[2]), "+f"(c[3])
    : "r"(a[0]), "r"(a[1]), "r"(a[2]), "r"(a[3]), "r"(b0), "r"(b1));
}

__global__ void __launch_bounds__(256,1) attn_kernel(float* __restrict__ out){
  extern __shared__ char sm_c[];
  char* sm = sm_c;
  char* smQ = sm + SQ_OFF;
  char* smK0 = sm + SK0_OFF;
  char* smK1 = sm + SK1_OFF;
  float* rsum = (float*)(sm + SRS_OFF);
  float* invp = (float*)(sm + SINV_OFF);

  const int tid = threadIdx.x;
  const int lane = tid & 31, wid = tid >> 5;
  const int wr = wid >> 1, wc = wid & 1;    // 4 row-warps x 2 col-warps
  const int g = lane >> 2, t = lane & 3;
  const int b = blockIdx.y, rb = blockIdx.x;

  const uint32_t smem_base = (uint32_t)__cvta_generic_to_shared(sm);

  // ldmatrix lane-address bases.
  // A (x4): m0=rows 0-7, m1=rows 8-15 (same col), m2/m3 = +16B col.
  //   row = warptile_row + (lane & 15); col16 = (lane>>4)&1
  const uint32_t aoff0 = (uint32_t)((wr*32 +  0 + (lane & 15))*SROW_B + ((lane >> 4) & 1)*16);
  const uint32_t aoff1 = (uint32_t)((wr*32 + 16 + (lane & 15))*SROW_B + ((lane >> 4) & 1)*16);
  // B (x4, two n-tiles of 8 rows): m0/m1 = rows ntp*16+0..7 (col 0, +16B), m2/m3 = rows +8.
  //   row = wc*64 + ntp*16 + (lane&7) + ((lane&16)?8:0); col16 = (lane&8)?16:0
  const uint32_t boff = (uint32_t)((wc*64 + (lane & 7) + ((lane >> 1) & 8))*SROW_B + (lane & 8)*2);

  const __nv_bfloat16* Qg = g_Q + ((size_t)b*NL + (size_t)rb*128)*NKE;
  const __nv_bfloat16* Kg = g_K + (size_t)b*NL*NKE;

  // prologue: Q + K chunk0 as group0, K chunk1 as group1
  stage_tile(smQ, Qg, tid);
  stage_tile(smK0, Kg, tid);
  cpcommit();
  stage_tile(smK1, Kg + (size_t)CHUNK*NKE, tid);
  cpcommit();

  float esum[2][2] = {{0.f,0.f},{0.f,0.f}};
  float vinv[2][2] = {{0.f,0.f},{0.f,0.f}};

  for (int pass = 0; pass < 2; pass++){
    if (pass == 1){
      stage_tile(smK0, Kg, tid); cpcommit();
      stage_tile(smK1, Kg + (size_t)CHUNK*NKE, tid); cpcommit();
    }
    for (int ci = 0; ci < NCH; ci++){
      cpwait1();
      __syncthreads();
      char* smKc = (ci & 1) ? smK1 : smK0;
      const uint32_t aA0 = smem_base + SQ_OFF + aoff0;
      const uint32_t aA1 = smem_base + SQ_OFF + aoff1;
      const uint32_t bB  = smem_base + ((ci & 1) ? SK1_OFF : SK0_OFF) + boff;

      float acc[2][8][4];
      #pragma unroll
      for (int mt=0;mt<2;mt++){
        #pragma unroll
        for (int nt=0;nt<8;nt++){
          #pragma unroll
          for (int i=0;i<4;i++) acc[mt][nt][i]=0.f;
        }
      }

      #pragma unroll
      for (int ks = 0; ks < 12; ks++){
        uint32_t a0[4], a1[4];
        ldsm4(a0, aA0 + ks*32);
        ldsm4(a1, aA1 + ks*32);
        #pragma unroll
        for (int ntp = 0; ntp < 4; ntp++){
          uint32_t br[4];
          ldsm4(br, bB + ntp*16*SROW_B + ks*32);
          mma16816(acc[0][2*ntp],   a0, br[0], br[1]);
          mma16816(acc[1][2*ntp],   a1, br[0], br[1]);
          mma16816(acc[0][2*ntp+1], a0, br[2], br[3]);
          mma16816(acc[1][2*ntp+1], a1, br[2], br[3]);
        }
      }
      __syncthreads();          // all warps done reading this K buffer
      int nx = ci + 2;
      if (nx < NCH) stage_tile(smKc, Kg + (size_t)nx*CHUNK*NKE, tid);
      cpcommit();               // commit (possibly empty) keeps group bookkeeping uniform

      if (pass == 0){
        #pragma unroll
        for (int mt=0;mt<2;mt++){
          #pragma unroll
          for (int nt=0;nt<8;nt++){
            float e0 = fexp2(acc[mt][nt][0]*SCALE_LOG2E);
            float e1 = fexp2(acc[mt][nt][1]*SCALE_LOG2E);
            float e2 = fexp2(acc[mt][nt][2]*SCALE_LOG2E);
            float e3 = fexp2(acc[mt][nt][3]*SCALE_LOG2E);
            esum[mt][0] += e0 + e1;
            esum[mt][1] += e2 + e3;
          }
        }
      } else {
        #pragma unroll
        for (int mt=0;mt<2;mt++){
          int r0 = rb*128 + wr*32 + mt*16 + g;
          float* o0 = out + ((size_t)b*NL + r0)*NL + ci*CHUNK + wc*64 + t*2;
          float* o1 = o0 + (size_t)8*NL;
          #pragma unroll
          for (int nt=0;nt<8;nt++){
            float w00 = fexp2(acc[mt][nt][0]*SCALE_LOG2E)*vinv[mt][0];
            float w01 = fexp2(acc[mt][nt][1]*SCALE_LOG2E)*vinv[mt][0];
            float w10 = fexp2(acc[mt][nt][2]*SCALE_LOG2E)*vinv[mt][1];
            float w11 = fexp2(acc[mt][nt][3]*SCALE_LOG2E)*vinv[mt][1];
            float2 v0 = make_float2(w00 > THRESH ? w00 : 0.f, w01 > THRESH ? w01 : 0.f);
            float2 v1 = make_float2(w10 > THRESH ? w10 : 0.f, w11 > THRESH ? w11 : 0.f);
            *(float2*)(o0 + nt*8) = v0;
            *(float2*)(o1 + nt*8) = v1;
          }
        }
      }
    }

    if (pass == 0){
      // reduce exp-sums across the quad (lanes sharing a row), publish, combine wc halves
      #pragma unroll
      for (int mt=0;mt<2;mt++){
        #pragma unroll
        for (int hh=0;hh<2;hh++){
          float v = esum[mt][hh];
          v += __shfl_xor_sync(0xffffffffu, v, 1);
          v += __shfl_xor_sync(0xffffffffu, v, 2);
          esum[mt][hh] = v;
        }
      }
      if (t == 0){
        #pragma unroll
        for (int mt=0;mt<2;mt++){
          rsum[wc*128 + wr*32 + mt*16 + g]     = esum[mt][0];
          rsum[wc*128 + wr*32 + mt*16 + g + 8] = esum[mt][1];
        }
      }
      __syncthreads();
      if (tid < 128) invp[tid] = 1.0f / (rsum[tid] + rsum[128 + tid]);
      __syncthreads();
      #pragma unroll
      for (int mt=0;mt<2;mt++){
        vinv[mt][0] = invp[wr*32 + mt*16 + g];
        vinv[mt][1] = invp[wr*32 + mt*16 + g + 8];
      }
    }
  }
}

// ---------------- launch ----------------
extern "C" void kernel_launch(void* const* d_in, const int* in_sizes, int n_in,
                              void* d_out, int out_size){
  const float* q  = (const float*)d_in[0];
  const float* k  = (const float*)d_in[1];
  const float* W1 = (const float*)d_in[2];
  const float* W2 = (const float*)d_in[3];
  float* out = (float*)d_out;

  cudaFuncSetAttribute(proj_kernel, cudaFuncAttributeMaxDynamicSharedMemorySize, SA_BYTES);
  cudaFuncSetAttribute(attn_kernel, cudaFuncAttributeMaxDynamicSharedMemorySize, SB_TOTAL);

  proj_kernel<<<2*NB*NL/PJ_POS, 256, SA_BYTES>>>(q, k, W1, W2);
  attn_kernel<<<dim3(NL/128, NB), 256, SB_TOTAL>>>(out);
}

// round 4
// speedup vs baseline: 1.1834x; 1.1834x over previous
#include <cuda_runtime.h>
#include <cuda_bf16.h>
#include <cstdint>
#include <cstddef>

#define NB   4
#define NC   64
#define NL   4096
#define NH   128
#define NKE  192          // [hi|x|x] split-bf16 extended K dimension

#define SCALE_LOG2E 14.4269504088896340737f   // 10 * log2(e)
#define THRESH 1e-3f

// ---------------- device scratch (no allocations allowed) ----------------
__device__ __align__(256) __nv_bfloat16 g_Q[NB*NL*NKE];   // [b][l][192] = [qhi|qlo|qhi]
__device__ __align__(256) __nv_bfloat16 g_K[NB*NL*NKE];   // [b][l][192] = [khi|khi|klo]

// ---------------- projection + leakyrelu + projection + l2norm + bf16 split ----------------
#define PJ_POS 32
#define HS_STR 132
#define W1_PITCH 65
#define W2_PITCH 129
#define SA_W1 0
#define SA_W2 (NH*W1_PITCH)                       // 8320
#define SA_XS (SA_W2 + NC*W2_PITCH)               // 8320+8256=16576
#define SA_HS (SA_XS + NC*PJ_POS)                 // +2048=18624
#define SA_FLOATS (SA_HS + PJ_POS*HS_STR)         // +4224=22848
#define SA_BYTES (SA_FLOATS*4)

__global__ void __launch_bounds__(256) proj_kernel(const float* __restrict__ xq,
                                                   const float* __restrict__ xk,
                                                   const float* __restrict__ W1,
                                                   const float* __restrict__ W2){
  extern __shared__ float sm_f[];
  float* sm = sm_f;
  const int tid = threadIdx.x;
  const int bpt = NL / PJ_POS;                 // 128 blocks per (tensor,batch)
  const int tb  = blockIdx.x / bpt;            // 0..7  (0..3 = query, 4..7 = key)
  const int l0  = (blockIdx.x % bpt) * PJ_POS;
  const bool isQ = (tb < NB);
  const int b   = tb & 3;
  const float* __restrict__ src = isQ ? xq : xk;
  __nv_bfloat16* __restrict__ dst = isQ ? g_Q : g_K;

  // native-layout weights, odd pitch (coalesced global, conflict-free smem)
  for (int i = tid; i < NH*NC; i += 256){
    int j = i >> 6, c = i & 63;
    sm[SA_W1 + j*W1_PITCH + c] = W1[i];        // W1[j][c]
  }
  for (int i = tid; i < NC*NH; i += 256){
    int o = i >> 7, j = i & 127;
    sm[SA_W2 + o*W2_PITCH + j] = W2[i];        // W2[o][j]
  }
  for (int i = tid; i < NC*PJ_POS; i += 256){
    int c = i >> 5, p = i & 31;
    sm[SA_XS + i] = src[((size_t)b*NC + c)*NL + l0 + p];   // xs[c][p]
  }
  __syncthreads();

  const int lanegrp = tid & 31;   // j-group in phase1, o-group in phase2
  const int pg      = tid >> 5;   // 0..7 (4 positions each)

  // ---- phase 1: h = leakyrelu(W1 @ x) ----
  // lane owns j = lanegrp + ji*32 (ji 0..3); warp owns positions pg*4..pg*4+3
  {
    float acc[4][4];
    #pragma unroll
    for (int ji=0;ji<4;ji++){
      #pragma unroll
      for (int pi=0;pi<4;pi++) acc[ji][pi]=0.f;
    }
    #pragma unroll 4
    for (int c=0;c<NC;c++){
      float w[4];
      #pragma unroll
      for (int ji=0;ji<4;ji++)
        w[ji] = sm[SA_W1 + (lanegrp + ji*32)*W1_PITCH + c];   // Δlane=65 -> conflict-free
      const float* xr = &sm[SA_XS + c*PJ_POS + pg*4];         // broadcast within warp
      #pragma unroll
      for (int pi=0;pi<4;pi++){
        float xv = xr[pi];
        #pragma unroll
        for (int ji=0;ji<4;ji++) acc[ji][pi] += w[ji]*xv;
      }
    }
    #pragma unroll
    for (int pi=0;pi<4;pi++){
      #pragma unroll
      for (int ji=0;ji<4;ji++){
        float v = acc[ji][pi];
        v = v >= 0.f ? v : 0.01f*v;
        sm[SA_HS + (pg*4+pi)*HS_STR + lanegrp + ji*32] = v;   // consecutive lanes
      }
    }
  }
  __syncthreads();

  // ---- phase 2: y = W2 @ h ; normalize ; split to bf16 ----
  // lane owns o = lanegrp, lanegrp+32
  {
    float acc[2][4];
    #pragma unroll
    for (int oi=0;oi<2;oi++){
      #pragma unroll
      for (int pi=0;pi<4;pi++) acc[oi][pi]=0.f;
    }
    #pragma unroll 4
    for (int j=0;j<NH;j++){
      float w0 = sm[SA_W2 + lanegrp*W2_PITCH + j];            // Δlane=129 -> conflict-free
      float w1 = sm[SA_W2 + (lanegrp+32)*W2_PITCH + j];
      const float* hr = &sm[SA_HS + pg*4*HS_STR + j];         // broadcast
      #pragma unroll
      for (int pi=0;pi<4;pi++){
        float hv = hr[pi*HS_STR];
        acc[0][pi] += w0*hv;
        acc[1][pi] += w1*hv;
      }
    }
    #pragma unroll
    for (int pi=0;pi<4;pi++){
      float ssq = acc[0][pi]*acc[0][pi] + acc[1][pi]*acc[1][pi];
      #pragma unroll
      for (int off=16; off; off>>=1) ssq += __shfl_xor_sync(0xffffffffu, ssq, off);
      float inv = 1.0f / fmaxf(sqrtf(ssq), 1e-12f);
      int p = pg*4 + pi;
      size_t rowbase = ((size_t)b*NL + l0 + p) * NKE;
      #pragma unroll
      for (int oi=0;oi<2;oi++){
        int o = lanegrp + oi*32;
        float v = acc[oi][pi] * inv;
        __nv_bfloat16 hi = __float2bfloat16(v);
        __nv_bfloat16 lo = __float2bfloat16(v - __bfloat162float(hi));
        if (isQ){
          dst[rowbase + o]       = hi;   // seg0: qhi
          dst[rowbase + 64 + o]  = lo;   // seg1: qlo
          dst[rowbase + 128 + o] = hi;   // seg2: qhi
        } else {
          dst[rowbase + o]       = hi;   // seg0: khi
          dst[rowbase + 64 + o]  = hi;   // seg1: khi
          dst[rowbase + 128 + o] = lo;   // seg2: klo
        }
      }
    }
  }
}

// ---------------- attention: scores GEMM + softmax + threshold ----------------
#define ATH   512            // 16 warps
#define CHUNK 128
#define NCH   (NL/CHUNK)     // 32
#define SROW_B 400           // padded smem row stride (192*2=384 data + 16 pad)
#define SQ_OFF  0
#define SK0_OFF 51200
#define SK1_OFF 102400
#define SRS_OFF 153600       // float rsum[4][128]
#define SINV_OFF (SRS_OFF + 4*128*4)   // 155648
#define SB_TOTAL (SINV_OFF + 128*4)    // 156160

__device__ __forceinline__ float fexp2(float x){
  float y;
  asm("ex2.approx.ftz.f32 %0, %1;" : "=f"(y) : "f"(x));
  return y;
}

__device__ __forceinline__ void cpa16(void* sptr, const void* gptr){
  uint32_t s = (uint32_t)__cvta_generic_to_shared(sptr);
  asm volatile("cp.async.cg.shared.global [%0], [%1], 16;" :: "r"(s), "l"(gptr));
}
__device__ __forceinline__ void cpcommit(){ asm volatile("cp.async.commit_group;"); }
__device__ __forceinline__ void cpwait1(){ asm volatile("cp.async.wait_group 1;"); }

// stage 128 rows of 384B (global, dense) into smem (stride 400B), 512 threads
__device__ __forceinline__ void stage_tile(char* sdst, const __nv_bfloat16* gsrc, int tid){
  const char* gb = (const char*)gsrc;
  #pragma unroll
  for (int i = 0; i < 6; i++){
    int idx = tid + i*ATH;
    int r = idx / 24, o = idx % 24;
    cpa16(sdst + r*SROW_B + o*16, gb + (size_t)r*384 + o*16);
  }
}

__device__ __forceinline__ void ldsm4(uint32_t (&r)[4], uint32_t saddr){
  asm volatile("ldmatrix.sync.aligned.m8n8.x4.shared.b16 {%0,%1,%2,%3}, [%4];"
    : "=r"(r[0]), "=r"(r[1]), "=r"(r[2]), "=r"(r[3]) : "r"(saddr));
}

__device__ __forceinline__ void mma16816(float (&c)[4], const uint32_t (&a)[4],
                                         uint32_t b0, uint32_t b1){
  asm volatile(
    "mma.sync.aligned.m16n8k16.row.col.f32.bf16.bf16.f32 "
    "{%0,%1,%2,%3}, {%4,%5,%6,%7}, {%8,%9}, {%0,%1,%2,%3};"
    : "+f"(c[0]), "+f"(c[1]), "+f"(c[2]), "+f"(c[3])
    : "r"(a[0]), "r"(a[1]), "r"(a[2]), "r"(a[3]), "r"(b0), "r"(b1));
}

__global__ void __launch_bounds__(ATH,1) attn_kernel(float* __restrict__ out){
  extern __shared__ char sm_c[];
  char* sm = sm_c;
  char* smQ = sm + SQ_OFF;
  float* rsum = (float*)(sm + SRS_OFF);
  float* invp = (float*)(sm + SINV_OFF);

  const int tid = threadIdx.x;
  const int lane = tid & 31, wid = tid >> 5;
  const int wr = wid >> 2, wc = wid & 3;    // 4 row-warps x 4 col-warps
  const int g = lane >> 2, t = lane & 3;
  const int b = blockIdx.y, rb = blockIdx.x;

  const uint32_t smem_base = (uint32_t)__cvta_generic_to_shared(sm);

  // ldmatrix lane-address bases.
  const uint32_t aoff0 = (uint32_t)((wr*32 +  0 + (lane & 15))*SROW_B + ((lane >> 4) & 1)*16);
  const uint32_t aoff1 = (uint32_t)((wr*32 + 16 + (lane & 15))*SROW_B + ((lane >> 4) & 1)*16);
  // B: warp covers cols wc*32..wc*32+31 (two 16-row ldsm4 groups)
  const uint32_t boff = (uint32_t)((wc*32 + (lane & 7) + ((lane >> 1) & 8))*SROW_B + (lane & 8)*2);

  const __nv_bfloat16* Qg = g_Q + ((size_t)b*NL + (size_t)rb*128)*NKE;
  const __nv_bfloat16* Kg = g_K + (size_t)b*NL*NKE;

  // prologue: Q + K chunk0 as group0, K chunk1 as group1
  stage_tile(smQ, Qg, tid);
  stage_tile(sm + SK0_OFF, Kg, tid);
  cpcommit();
  stage_tile(sm + SK1_OFF, Kg + (size_t)CHUNK*NKE, tid);
  cpcommit();

  float esum[2][2] = {{0.f,0.f},{0.f,0.f}};
  float vinv[2][2] = {{0.f,0.f},{0.f,0.f}};

  for (int pass = 0; pass < 2; pass++){
    if (pass == 1){
      stage_tile(sm + SK0_OFF, Kg, tid); cpcommit();
      stage_tile(sm + SK1_OFF, Kg + (size_t)CHUNK*NKE, tid); cpcommit();
    }
    for (int ci = 0; ci < NCH; ci++){
      cpwait1();
      __syncthreads();
      char* smKc = sm + ((ci & 1) ? SK1_OFF : SK0_OFF);
      const uint32_t aA0 = smem_base + SQ_OFF + aoff0;
      const uint32_t aA1 = smem_base + SQ_OFF + aoff1;
      const uint32_t bB  = smem_base + ((ci & 1) ? SK1_OFF : SK0_OFF) + boff;

      float acc[2][4][4];
      #pragma unroll
      for (int mt=0;mt<2;mt++){
        #pragma unroll
        for (int nt=0;nt<4;nt++){
          #pragma unroll
          for (int i=0;i<4;i++) acc[mt][nt][i]=0.f;
        }
      }

      #pragma unroll
      for (int ks = 0; ks < 12; ks++){
        uint32_t a0[4], a1[4];
        ldsm4(a0, aA0 + ks*32);
        ldsm4(a1, aA1 + ks*32);
        #pragma unroll
        for (int ntp = 0; ntp < 2; ntp++){
          uint32_t br[4];
          ldsm4(br, bB + ntp*16*SROW_B + ks*32);
          mma16816(acc[0][2*ntp],   a0, br[0], br[1]);
          mma16816(acc[1][2*ntp],   a1, br[0], br[1]);
          mma16816(acc[0][2*ntp+1], a0, br[2], br[3]);
          mma16816(acc[1][2*ntp+1], a1, br[2], br[3]);
        }
      }
      __syncthreads();          // all warps done reading this K buffer
      int nx = ci + 2;
      if (nx < NCH) stage_tile(smKc, Kg + (size_t)nx*CHUNK*NKE, tid);
      cpcommit();               // uniform group bookkeeping

      if (pass == 0){
        #pragma unroll
        for (int mt=0;mt<2;mt++){
          #pragma unroll
          for (int nt=0;nt<4;nt++){
            float e0 = fexp2(acc[mt][nt][0]*SCALE_LOG2E);
            float e1 = fexp2(acc[mt][nt][1]*SCALE_LOG2E);
            float e2 = fexp2(acc[mt][nt][2]*SCALE_LOG2E);
            float e3 = fexp2(acc[mt][nt][3]*SCALE_LOG2E);
            esum[mt][0] += e0 + e1;
            esum[mt][1] += e2 + e3;
          }
        }
      } else {
        #pragma unroll
        for (int mt=0;mt<2;mt++){
          int r0 = rb*128 + wr*32 + mt*16 + g;
          float* o0 = out + ((size_t)b*NL + r0)*NL + ci*CHUNK + wc*32 + t*2;
          float* o1 = o0 + (size_t)8*NL;
          #pragma unroll
          for (int nt=0;nt<4;nt++){
            float w00 = fexp2(acc[mt][nt][0]*SCALE_LOG2E)*vinv[mt][0];
            float w01 = fexp2(acc[mt][nt][1]*SCALE_LOG2E)*vinv[mt][0];
            float w10 = fexp2(acc[mt][nt][2]*SCALE_LOG2E)*vinv[mt][1];
            float w11 = fexp2(acc[mt][nt][3]*SCALE_LOG2E)*vinv[mt][1];
            float2 v0 = make_float2(w00 > THRESH ? w00 : 0.f, w01 > THRESH ? w01 : 0.f);
            float2 v1 = make_float2(w10 > THRESH ? w10 : 0.f, w11 > THRESH ? w11 : 0.f);
            *(float2*)(o0 + nt*8) = v0;
            *(float2*)(o1 + nt*8) = v1;
          }
        }
      }
    }

    if (pass == 0){
      // quad-reduce within rows, publish per-wc partial sums, combine 4 halves
      #pragma unroll
      for (int mt=0;mt<2;mt++){
        #pragma unroll
        for (int hh=0;hh<2;hh++){
          float v = esum[mt][hh];
          v += __shfl_xor_sync(0xffffffffu, v, 1);
          v += __shfl_xor_sync(0xffffffffu, v, 2);
          esum[mt][hh] = v;
        }
      }
      if (t == 0){
        #pragma unroll
        for (int mt=0;mt<2;mt++){
          rsum[wc*128 + wr*32 + mt*16 + g]     = esum[mt][0];
          rsum[wc*128 + wr*32 + mt*16 + g + 8] = esum[mt][1];
        }
      }
      __syncthreads();
      if (tid < 128)
        invp[tid] = 1.0f / (rsum[tid] + rsum[128 + tid] + rsum[256 + tid] + rsum[384 + tid]);
      __syncthreads();
      #pragma unroll
      for (int mt=0;mt<2;mt++){
        vinv[mt][0] = invp[wr*32 + mt*16 + g];
        vinv[mt][1] = invp[wr*32 + mt*16 + g + 8];
      }
    }
  }
}

// ---------------- launch ----------------
extern "C" void kernel_launch(void* const* d_in, const int* in_sizes, int n_in,
                              void* d_out, int out_size){
  const float* q  = (const float*)d_in[0];
  const float* k  = (const float*)d_in[1];
  const float* W1 = (const float*)d_in[2];
  const float* W2 = (const float*)d_in[3];
  float* out = (float*)d_out;

  cudaFuncSetAttribute(proj_kernel, cudaFuncAttributeMaxDynamicSharedMemorySize, SA_BYTES);
  cudaFuncSetAttribute(attn_kernel, cudaFuncAttributeMaxDynamicSharedMemorySize, SB_TOTAL);

  proj_kernel<<<2*NB*NL/PJ_POS, 256, SA_BYTES>>>(q, k, W1, W2);
  attn_kernel<<<dim3(NL/128, NB), ATH, SB_TOTAL>>>(out);
}